// round 1
// baseline (speedup 1.0000x reference)
#include <cuda_runtime.h>
#include <math.h>

#define BSZ   8
#define TSEQ  2048
#define CDIM  1024
#define HD    64

// scratch for projected q, k, v  (4 MB each)
__device__ float g_q[BSZ * TSEQ * HD];
__device__ float g_k[BSZ * TSEQ * HD];
__device__ float g_v[BSZ * TSEQ * HD];

// ---------------------------------------------------------------------------
// Kernel 1: QKV projection.  kqv = x @ W + b, columns [0:64)=k, [64:128)=q,
// [128:192)=v  (reference splits as k, q, v in that order).
// GEMM M=16384, N=192, K=1024.  BM=128, BN=64, BK=16, 256 threads,
// 8x4 micro-tile per thread.
// ---------------------------------------------------------------------------
__global__ __launch_bounds__(256) void qkv_proj_kernel(
    const float* __restrict__ x,   // [16384, 1024]
    const float* __restrict__ W,   // [1024, 192]
    const float* __restrict__ b)   // [192]
{
    __shared__ float As[16][132];   // [BK][BM+pad], k-major for compute
    __shared__ float Bs[16][68];    // [BK][BN+pad]

    const int bm  = blockIdx.x;     // 0..127
    const int bn  = blockIdx.y;     // 0..2  -> k / q / v
    const int tid = threadIdx.x;

    const int tr = tid >> 4;        // 0..15
    const int tc = tid & 15;        // 0..15
    const int row0 = tr * 8;
    const int col0 = tc * 4;

    const float* xblk = x + (size_t)bm * 128 * CDIM;
    const float* wblk = W + bn * 64;

    float acc[8][4];
#pragma unroll
    for (int i = 0; i < 8; i++)
#pragma unroll
        for (int j = 0; j < 4; j++) acc[i][j] = 0.f;

    for (int k0 = 0; k0 < CDIM; k0 += 16) {
        // Load A tile: 128 rows x 16 k -> 512 float4, 2 per thread
#pragma unroll
        for (int i = 0; i < 2; i++) {
            int idx = i * 256 + tid;          // 0..511
            int r   = idx >> 2;               // row 0..127
            int kk  = (idx & 3) * 4;          // 0,4,8,12
            float4 v4 = *reinterpret_cast<const float4*>(
                xblk + (size_t)r * CDIM + k0 + kk);
            As[kk + 0][r] = v4.x;
            As[kk + 1][r] = v4.y;
            As[kk + 2][r] = v4.z;
            As[kk + 3][r] = v4.w;
        }
        // Load B tile: 16 k-rows x 64 cols -> 256 float4, 1 per thread
        {
            int kr = tid >> 4;                // 0..15
            int nc = (tid & 15) * 4;          // 0..60
            float4 v4 = *reinterpret_cast<const float4*>(
                wblk + (size_t)(k0 + kr) * 192 + nc);
            *reinterpret_cast<float4*>(&Bs[kr][nc]) = v4;
        }
        __syncthreads();

#pragma unroll
        for (int kk = 0; kk < 16; kk++) {
            float4 a0 = *reinterpret_cast<const float4*>(&As[kk][row0]);
            float4 a1 = *reinterpret_cast<const float4*>(&As[kk][row0 + 4]);
            float4 bf = *reinterpret_cast<const float4*>(&Bs[kk][col0]);
            float a[8] = {a0.x, a0.y, a0.z, a0.w, a1.x, a1.y, a1.z, a1.w};
            float bb[4] = {bf.x, bf.y, bf.z, bf.w};
#pragma unroll
            for (int i = 0; i < 8; i++)
#pragma unroll
                for (int j = 0; j < 4; j++)
                    acc[i][j] = fmaf(a[i], bb[j], acc[i][j]);
        }
        __syncthreads();
    }

    // epilogue: add bias, scatter to k/q/v
    float bias[4];
#pragma unroll
    for (int j = 0; j < 4; j++) bias[j] = b[bn * 64 + col0 + j];

    float* outbuf = (bn == 0) ? g_k : (bn == 1) ? g_q : g_v;
#pragma unroll
    for (int i = 0; i < 8; i++) {
        float4 o;
        o.x = acc[i][0] + bias[0];
        o.y = acc[i][1] + bias[1];
        o.z = acc[i][2] + bias[2];
        o.w = acc[i][3] + bias[3];
        *reinterpret_cast<float4*>(
            outbuf + (size_t)(bm * 128 + row0 + i) * HD + col0) = o;
    }
}

// ---------------------------------------------------------------------------
// Kernel 2: causal flash attention, fp32.
// Block: 256 threads, BM=64 query rows (4 threads per row, each owning a
// 16-wide head-dim slice).  Key tiles BN=64.  Streaming softmax.
// Grid: (TSEQ/BM, BSZ) = (32, 8).
// ---------------------------------------------------------------------------
#define ABM 64
#define ABN 64

__global__ __launch_bounds__(256) void attn_kernel(float* __restrict__ out)
{
    __shared__ float k_s[ABN][HD];        // 16 KB
    __shared__ float v_s[ABN][HD];        // 16 KB
    __shared__ float p_s[ABM][ABN + 1];   // padded -> conflict-free row reads

    const int qt  = blockIdx.x;
    const int bb  = blockIdx.y;
    const int tid = threadIdx.x;
    const int r   = tid >> 2;             // query row in tile, 0..63
    const int h   = tid & 3;              // head-dim quarter, 0..3
    const int qrow_g = qt * ABM + r;

    const float* qptr = g_q + ((size_t)bb * TSEQ + qt * ABM) * HD;
    const float* kptr = g_k + (size_t)bb * TSEQ * HD;
    const float* vptr = g_v + (size_t)bb * TSEQ * HD;

    // q fragment: q[r][h*16 .. h*16+15]
    float4 qf[4];
#pragma unroll
    for (int i = 0; i < 4; i++)
        qf[i] = *reinterpret_cast<const float4*>(qptr + r * HD + h * 16 + i * 4);

    float of[16];
#pragma unroll
    for (int i = 0; i < 16; i++) of[i] = 0.f;
    float m = -INFINITY, l = 0.f;
    const float scale = 0.125f;           // 64^-0.5

    const int kend = (qt + 1) * ABM;      // causal: keys 0..qrow inclusive

    for (int t0 = 0; t0 < kend; t0 += ABN) {
        // load K and V tiles (each 64x64 f32 = 1024 float4; 4 per thread each)
#pragma unroll
        for (int i = 0; i < 4; i++) {
            int idx = i * 256 + tid;       // 0..1023
            int rr  = idx >> 4;            // 0..63
            int cc  = (idx & 15) * 4;      // 0..60
            *reinterpret_cast<float4*>(&k_s[rr][cc]) =
                *reinterpret_cast<const float4*>(kptr + (size_t)(t0 + rr) * HD + cc);
            *reinterpret_cast<float4*>(&v_s[rr][cc]) =
                *reinterpret_cast<const float4*>(vptr + (size_t)(t0 + rr) * HD + cc);
        }
        __syncthreads();

        float tmax = -INFINITY;
        float sf[16];
#pragma unroll 4
        for (int j = 0; j < ABN; j++) {
            const float4* kv = reinterpret_cast<const float4*>(&k_s[j][h * 16]);
            float p0 = 0.f, p1 = 0.f;
#pragma unroll
            for (int i = 0; i < 4; i += 2) {
                float4 ka = kv[i], kb = kv[i + 1];
                p0 = fmaf(qf[i].x, ka.x, p0); p0 = fmaf(qf[i].y, ka.y, p0);
                p0 = fmaf(qf[i].z, ka.z, p0); p0 = fmaf(qf[i].w, ka.w, p0);
                p1 = fmaf(qf[i+1].x, kb.x, p1); p1 = fmaf(qf[i+1].y, kb.y, p1);
                p1 = fmaf(qf[i+1].z, kb.z, p1); p1 = fmaf(qf[i+1].w, kb.w, p1);
            }
            float p = p0 + p1;
            p += __shfl_xor_sync(0xffffffffu, p, 1);
            p += __shfl_xor_sync(0xffffffffu, p, 2);
            p *= scale;
            if (t0 + j > qrow_g) p = -INFINITY;   // causal mask
            tmax = fmaxf(tmax, p);
            if ((j & 3) == h) sf[j >> 2] = p;     // keep owned quarter
        }

        float mnew = fmaxf(m, tmax);              // finite: j=0 always valid
        float corr = expf(m - mnew);              // 0 on first tile
        float lsum = 0.f;
        float pf[16];
#pragma unroll
        for (int i = 0; i < 16; i++) {
            float e = expf(sf[i] - mnew);
            pf[i] = e;
            lsum += e;
        }
        lsum += __shfl_xor_sync(0xffffffffu, lsum, 1);
        lsum += __shfl_xor_sync(0xffffffffu, lsum, 2);
        l = l * corr + lsum;
        m = mnew;
#pragma unroll
        for (int i = 0; i < 16; i++) of[i] *= corr;

        // stage probabilities (quad-private row, same warp)
#pragma unroll
        for (int i = 0; i < 16; i++) p_s[r][i * 4 + h] = pf[i];
        __syncwarp();

        // PV accumulate
#pragma unroll 2
        for (int j = 0; j < ABN; j++) {
            float p = p_s[r][j];
            const float4* vv = reinterpret_cast<const float4*>(&v_s[j][h * 16]);
#pragma unroll
            for (int i = 0; i < 4; i++) {
                float4 v4 = vv[i];
                of[i * 4 + 0] = fmaf(p, v4.x, of[i * 4 + 0]);
                of[i * 4 + 1] = fmaf(p, v4.y, of[i * 4 + 1]);
                of[i * 4 + 2] = fmaf(p, v4.z, of[i * 4 + 2]);
                of[i * 4 + 3] = fmaf(p, v4.w, of[i * 4 + 3]);
            }
        }
        __syncthreads();
    }

    // finalize: divide by row sum, store
    float inv = 1.f / l;
    float* optr = out + ((size_t)bb * TSEQ + qrow_g) * HD + h * 16;
#pragma unroll
    for (int i = 0; i < 4; i++) {
        float4 o;
        o.x = of[i * 4 + 0] * inv;
        o.y = of[i * 4 + 1] * inv;
        o.z = of[i * 4 + 2] * inv;
        o.w = of[i * 4 + 3] * inv;
        *reinterpret_cast<float4*>(optr + i * 4) = o;
    }
}

// ---------------------------------------------------------------------------
extern "C" void kernel_launch(void* const* d_in, const int* in_sizes, int n_in,
                              void* d_out, int out_size)
{
    const float* x = (const float*)d_in[0];   // [8, 2048, 1024]
    const float* W = (const float*)d_in[1];   // [1024, 192]
    const float* b = (const float*)d_in[2];   // [192]
    float* out = (float*)d_out;               // [8, 2048, 64]

    (void)in_sizes; (void)n_in; (void)out_size;

    dim3 g1((BSZ * TSEQ) / 128, 3);
    qkv_proj_kernel<<<g1, 256>>>(x, W, b);

    dim3 g2(TSEQ / ABM, BSZ);
    attn_kernel<<<g2, 256>>>(out);
}

// round 2
// speedup vs baseline: 3.8548x; 3.8548x over previous
#include <cuda_runtime.h>
#include <math.h>

#define BSZ   8
#define TSEQ  2048
#define CDIM  1024
#define HD    64

typedef unsigned long long ull;

// scratch for projected q, k, v  (4 MB each)
__device__ float g_q[BSZ * TSEQ * HD];
__device__ float g_k[BSZ * TSEQ * HD];
__device__ float g_v[BSZ * TSEQ * HD];

// ---- packed f32x2 helpers (sm_103a dual-rate fp32) -------------------------
__device__ __forceinline__ ull pk2(float lo, float hi) {
    ull r; asm("mov.b64 %0, {%1, %2};" : "=l"(r) : "f"(lo), "f"(hi)); return r;
}
__device__ __forceinline__ ull dup2(float v) { return pk2(v, v); }
__device__ __forceinline__ ull ffma2(ull a, ull b, ull c) {
    ull d; asm("fma.rn.f32x2 %0, %1, %2, %3;" : "=l"(d) : "l"(a), "l"(b), "l"(c)); return d;
}
__device__ __forceinline__ ull fmul2(ull a, ull b) {
    ull d; asm("mul.rn.f32x2 %0, %1, %2;" : "=l"(d) : "l"(a), "l"(b)); return d;
}
__device__ __forceinline__ float2 up2(ull v) {
    float lo, hi; asm("mov.b64 {%0, %1}, %2;" : "=f"(lo), "=f"(hi) : "l"(v));
    float2 f; f.x = lo; f.y = hi; return f;
}

// swizzle: minor index XOR'd with bits of major index -> conflict-free transposes
#define SWZ(maj, mn) ((mn) ^ ((((maj) >> 2) & 7) << 2))

// ---------------------------------------------------------------------------
// Kernel 1: QKV projection.  kqv = x @ W + b, bn: 0=k, 1=q, 2=v.
// M=16384, N=192(3x64), K=1024. BM=128, BN=64, BK=16, 256 threads, 8x4 tile.
// Inner loop uses packed FFMA2 (pairs over rows).
// ---------------------------------------------------------------------------
__global__ __launch_bounds__(256) void qkv_proj_kernel(
    const float* __restrict__ x,
    const float* __restrict__ W,
    const float* __restrict__ b)
{
    __shared__ float As[16][132];
    __shared__ float Bs[16][68];

    const int bm  = blockIdx.x;
    const int bn  = blockIdx.y;
    const int tid = threadIdx.x;

    const int tr = tid >> 4;
    const int tc = tid & 15;
    const int row0 = tr * 8;
    const int col0 = tc * 4;

    const float* xblk = x + (size_t)bm * 128 * CDIM;
    const float* wblk = W + bn * 64;

    ull acc2[4][4];
#pragma unroll
    for (int i = 0; i < 4; i++)
#pragma unroll
        for (int j = 0; j < 4; j++) acc2[i][j] = 0ULL;

    for (int k0 = 0; k0 < CDIM; k0 += 16) {
#pragma unroll
        for (int i = 0; i < 2; i++) {
            int idx = i * 256 + tid;
            int r   = idx >> 2;
            int kk  = (idx & 3) * 4;
            float4 v4 = *reinterpret_cast<const float4*>(
                xblk + (size_t)r * CDIM + k0 + kk);
            As[kk + 0][r] = v4.x;
            As[kk + 1][r] = v4.y;
            As[kk + 2][r] = v4.z;
            As[kk + 3][r] = v4.w;
        }
        {
            int kr = tid >> 4;
            int nc = (tid & 15) * 4;
            float4 v4 = *reinterpret_cast<const float4*>(
                wblk + (size_t)(k0 + kr) * 192 + nc);
            *reinterpret_cast<float4*>(&Bs[kr][nc]) = v4;
        }
        __syncthreads();

#pragma unroll
        for (int kk = 0; kk < 16; kk++) {
            float4 a0 = *reinterpret_cast<const float4*>(&As[kk][row0]);
            float4 a1 = *reinterpret_cast<const float4*>(&As[kk][row0 + 4]);
            float4 bf = *reinterpret_cast<const float4*>(&Bs[kk][col0]);
            ull aP0 = pk2(a0.x, a0.y), aP1 = pk2(a0.z, a0.w);
            ull aP2 = pk2(a1.x, a1.y), aP3 = pk2(a1.z, a1.w);
            ull b0 = dup2(bf.x), b1 = dup2(bf.y), b2 = dup2(bf.z), b3 = dup2(bf.w);
            acc2[0][0] = ffma2(aP0, b0, acc2[0][0]);
            acc2[0][1] = ffma2(aP0, b1, acc2[0][1]);
            acc2[0][2] = ffma2(aP0, b2, acc2[0][2]);
            acc2[0][3] = ffma2(aP0, b3, acc2[0][3]);
            acc2[1][0] = ffma2(aP1, b0, acc2[1][0]);
            acc2[1][1] = ffma2(aP1, b1, acc2[1][1]);
            acc2[1][2] = ffma2(aP1, b2, acc2[1][2]);
            acc2[1][3] = ffma2(aP1, b3, acc2[1][3]);
            acc2[2][0] = ffma2(aP2, b0, acc2[2][0]);
            acc2[2][1] = ffma2(aP2, b1, acc2[2][1]);
            acc2[2][2] = ffma2(aP2, b2, acc2[2][2]);
            acc2[2][3] = ffma2(aP2, b3, acc2[2][3]);
            acc2[3][0] = ffma2(aP3, b0, acc2[3][0]);
            acc2[3][1] = ffma2(aP3, b1, acc2[3][1]);
            acc2[3][2] = ffma2(aP3, b2, acc2[3][2]);
            acc2[3][3] = ffma2(aP3, b3, acc2[3][3]);
        }
        __syncthreads();
    }

    float bias[4];
#pragma unroll
    for (int j = 0; j < 4; j++) bias[j] = b[bn * 64 + col0 + j];

    float* outbuf = (bn == 0) ? g_k : (bn == 1) ? g_q : g_v;
#pragma unroll
    for (int i = 0; i < 8; i++) {
        int ip = i >> 1;
        float2 f0 = up2(acc2[ip][0]);
        float2 f1 = up2(acc2[ip][1]);
        float2 f2 = up2(acc2[ip][2]);
        float2 f3 = up2(acc2[ip][3]);
        float4 o;
        o.x = ((i & 1) ? f0.y : f0.x) + bias[0];
        o.y = ((i & 1) ? f1.y : f1.x) + bias[1];
        o.z = ((i & 1) ? f2.y : f2.x) + bias[2];
        o.w = ((i & 1) ? f3.y : f3.x) + bias[3];
        *reinterpret_cast<float4*>(
            outbuf + (size_t)(bm * 128 + row0 + i) * HD + col0) = o;
    }
}

// ---------------------------------------------------------------------------
// Kernel 2: causal flash attention, fp32, register-tiled GEMMs, FFMA2.
// Block 256 thr handles two q-tiles (qt, 31-qt) -> exactly 33 key tiles each.
// Per key tile: GEMM1 S=Q@K^T (4x4 micro), row softmax (shfl only per-tile),
// GEMM2 O+=P@V. P overwrites K's smem. Grid (16, 8).
// ---------------------------------------------------------------------------
__global__ __launch_bounds__(256) void attn_kernel(float* __restrict__ out)
{
    __shared__ float q_s[64][64];    // [d][r^swz]  (q pre-scaled)
    __shared__ float kp_s[64][64];   // K: [d][j^swz]; reused as P: [j][r^swz]
    __shared__ float v_s[64][64];    // [j][c] row-major

    const int tid = threadIdx.x;
    const int tr = tid >> 4, tc = tid & 15;
    const int r0 = tr * 4, c0 = tc * 4, j0 = tc * 4;
    const int bb = blockIdx.y;

    const float* kg = g_k + (size_t)bb * TSEQ * HD;
    const float* vg = g_v + (size_t)bb * TSEQ * HD;

    for (int half = 0; half < 2; half++) {
        const int qt = half ? (31 - (int)blockIdx.x) : (int)blockIdx.x;
        const int qrow0 = qt * 64;
        const float* qg = g_q + ((size_t)bb * TSEQ + qrow0) * HD;

        __syncthreads();   // q_s free (prev half's GEMM1 readers done)
#pragma unroll
        for (int it = 0; it < 4; it++) {
            int idx = it * 256 + tid;
            int r = idx >> 4;
            int d = (idx & 15) << 2;
            float4 v4 = *reinterpret_cast<const float4*>(qg + (size_t)r * HD + d);
            int sw_r = SWZ(d, r);
            q_s[d + 0][sw_r] = v4.x * 0.125f;
            q_s[d + 1][sw_r] = v4.y * 0.125f;
            q_s[d + 2][sw_r] = v4.z * 0.125f;
            q_s[d + 3][sw_r] = v4.w * 0.125f;
        }

        ull o2[2][4] = {{0ULL,0ULL,0ULL,0ULL},{0ULL,0ULL,0ULL,0ULL}};
        float m[4] = {-1e30f, -1e30f, -1e30f, -1e30f};
        float l[4] = {0.f, 0.f, 0.f, 0.f};

        for (int kt = 0; kt <= qt; kt++) {
            const int t0 = kt * 64;
            __syncthreads();   // kp_s/v_s free; q_s visible on first iter
#pragma unroll
            for (int it = 0; it < 4; it++) {
                int idx = it * 256 + tid;
                int r = idx >> 4;
                int d = (idx & 15) << 2;
                float4 k4 = *reinterpret_cast<const float4*>(
                    kg + (size_t)(t0 + r) * HD + d);
                int sw_r = SWZ(d, r);
                kp_s[d + 0][sw_r] = k4.x;
                kp_s[d + 1][sw_r] = k4.y;
                kp_s[d + 2][sw_r] = k4.z;
                kp_s[d + 3][sw_r] = k4.w;
                *reinterpret_cast<float4*>(&v_s[r][d]) =
                    *reinterpret_cast<const float4*>(vg + (size_t)(t0 + r) * HD + d);
            }
            __syncthreads();

            // ---- GEMM1: S = Q @ K^T (rows paired in f32x2) ----
            ull s2[2][4] = {{0ULL,0ULL,0ULL,0ULL},{0ULL,0ULL,0ULL,0ULL}};
#pragma unroll 8
            for (int d = 0; d < 64; d++) {
                int sw = ((d >> 2) & 7) << 2;
                float4 a  = *reinterpret_cast<const float4*>(&q_s[d][r0 ^ sw]);
                float4 bv = *reinterpret_cast<const float4*>(&kp_s[d][j0 ^ sw]);
                ull a01 = pk2(a.x, a.y), a23 = pk2(a.z, a.w);
                ull b0 = dup2(bv.x), b1 = dup2(bv.y), b2 = dup2(bv.z), b3 = dup2(bv.w);
                s2[0][0] = ffma2(a01, b0, s2[0][0]);
                s2[0][1] = ffma2(a01, b1, s2[0][1]);
                s2[0][2] = ffma2(a01, b2, s2[0][2]);
                s2[0][3] = ffma2(a01, b3, s2[0][3]);
                s2[1][0] = ffma2(a23, b0, s2[1][0]);
                s2[1][1] = ffma2(a23, b1, s2[1][1]);
                s2[1][2] = ffma2(a23, b2, s2[1][2]);
                s2[1][3] = ffma2(a23, b3, s2[1][3]);
            }

            float s[4][4];
#pragma unroll
            for (int ip = 0; ip < 2; ip++)
#pragma unroll
                for (int j = 0; j < 4; j++) {
                    float2 f = up2(s2[ip][j]);
                    s[2 * ip + 0][j] = f.x;
                    s[2 * ip + 1][j] = f.y;
                }

            if (kt == qt) {   // diagonal tile: causal mask
#pragma unroll
                for (int i = 0; i < 4; i++)
#pragma unroll
                    for (int j = 0; j < 4; j++)
                        if (j0 + j > r0 + i) s[i][j] = -1e30f;
            }

            // ---- streaming softmax (row reduce over 16 tc-lanes) ----
            float mn[4], corr[4];
#pragma unroll
            for (int i = 0; i < 4; i++) {
                float mx = fmaxf(fmaxf(s[i][0], s[i][1]), fmaxf(s[i][2], s[i][3]));
#pragma unroll
                for (int o = 1; o < 16; o <<= 1)
                    mx = fmaxf(mx, __shfl_xor_sync(0xffffffffu, mx, o));
                mn[i]  = fmaxf(m[i], mx);
                corr[i] = __expf(m[i] - mn[i]);
                m[i]   = mn[i];
            }

            __syncthreads();   // all GEMM1 K reads done before P overwrites kp_s

            const int swp = (tc & 7) << 2;   // swizzle for p rows j0..j0+3
#pragma unroll
            for (int i = 0; i < 4; i++) {
                float r4 = 0.f;
#pragma unroll
                for (int j = 0; j < 4; j++) {
                    float e = __expf(s[i][j] - mn[i]);
                    r4 += e;
                    kp_s[j0 + j][(r0 + i) ^ swp] = e;
                }
#pragma unroll
                for (int o = 1; o < 16; o <<= 1)
                    r4 += __shfl_xor_sync(0xffffffffu, r4, o);
                l[i] = l[i] * corr[i] + r4;
            }

            ull c01 = pk2(corr[0], corr[1]), c23 = pk2(corr[2], corr[3]);
#pragma unroll
            for (int j = 0; j < 4; j++) {
                o2[0][j] = fmul2(o2[0][j], c01);
                o2[1][j] = fmul2(o2[1][j], c23);
            }
            __syncthreads();   // P visible to all

            // ---- GEMM2: O += P @ V ----
#pragma unroll 8
            for (int j = 0; j < 64; j++) {
                int sw = ((j >> 2) & 7) << 2;
                float4 a  = *reinterpret_cast<const float4*>(&kp_s[j][r0 ^ sw]);
                float4 bv = *reinterpret_cast<const float4*>(&v_s[j][c0]);
                ull a01 = pk2(a.x, a.y), a23 = pk2(a.z, a.w);
                ull b0 = dup2(bv.x), b1 = dup2(bv.y), b2 = dup2(bv.z), b3 = dup2(bv.w);
                o2[0][0] = ffma2(a01, b0, o2[0][0]);
                o2[0][1] = ffma2(a01, b1, o2[0][1]);
                o2[0][2] = ffma2(a01, b2, o2[0][2]);
                o2[0][3] = ffma2(a01, b3, o2[0][3]);
                o2[1][0] = ffma2(a23, b0, o2[1][0]);
                o2[1][1] = ffma2(a23, b1, o2[1][1]);
                o2[1][2] = ffma2(a23, b2, o2[1][2]);
                o2[1][3] = ffma2(a23, b3, o2[1][3]);
            }
        }

        // ---- finalize ----
#pragma unroll
        for (int i = 0; i < 4; i++) {
            float inv = 1.f / l[i];
            float2 f0 = up2(o2[i >> 1][0]);
            float2 f1 = up2(o2[i >> 1][1]);
            float2 f2 = up2(o2[i >> 1][2]);
            float2 f3 = up2(o2[i >> 1][3]);
            float4 o;
            o.x = ((i & 1) ? f0.y : f0.x) * inv;
            o.y = ((i & 1) ? f1.y : f1.x) * inv;
            o.z = ((i & 1) ? f2.y : f2.x) * inv;
            o.w = ((i & 1) ? f3.y : f3.x) * inv;
            *reinterpret_cast<float4*>(
                out + ((size_t)bb * TSEQ + qrow0 + r0 + i) * HD + c0) = o;
        }
    }
}

// ---------------------------------------------------------------------------
extern "C" void kernel_launch(void* const* d_in, const int* in_sizes, int n_in,
                              void* d_out, int out_size)
{
    const float* x = (const float*)d_in[0];
    const float* W = (const float*)d_in[1];
    const float* b = (const float*)d_in[2];
    float* out = (float*)d_out;

    (void)in_sizes; (void)n_in; (void)out_size;

    dim3 g1((BSZ * TSEQ) / 128, 3);
    qkv_proj_kernel<<<g1, 256>>>(x, W, b);

    dim3 g2(16, BSZ);
    attn_kernel<<<g2, 256>>>(out);
}